// round 3
// baseline (speedup 1.0000x reference)
#include <cuda_runtime.h>
#include <math.h>

#define N_REGIONS 10
#define HIDDEN    128
#define HEADS     4
#define N_LAYERS  3
#define CHPR      7
#define TOKENS    16384
#define TB        4            // tokens per block
#define NTHREADS  512
typedef unsigned long long u64;

// neighbor lists: c_nbr[i][q] = j such that edge j->i exists (incl self loop)
__constant__ int c_nbr_cnt[N_REGIONS] = {5,5,5,3,3,4,3,4,2,2};
__constant__ int c_nbr[N_REGIONS][5] = {
    {0,1,2,3,4},    // prefrontal
    {0,1,2,5,7},    // broca
    {0,1,2,3,7},    // wernicke
    {0,2,3,0,0},    // visual
    {0,4,5,0,0},    // premotor
    {1,4,5,6,0},    // primary_motor
    {5,6,9,0,0},    // primary_sensory
    {1,2,7,8,0},    // auditory
    {7,8,0,0,0},    // auditory_assoc
    {6,9,0,0,0}     // somatic_sensory
};

// k-pair-major transposed GAT weights: g_Wt[l][m][col] = {W[2m][col], W[2m+1][col]}
__device__ u64 g_Wt[N_LAYERS * 64 * 512];

__device__ __forceinline__ float gelu_exact(float v) {
    return 0.5f * v * (1.0f + erff(v * 0.70710678118654752f));
}
__device__ __forceinline__ u64 ffma2(u64 a, u64 b, u64 c) {
    u64 d; asm("fma.rn.f32x2 %0, %1, %2, %3;" : "=l"(d) : "l"(a), "l"(b), "l"(c)); return d;
}
__device__ __forceinline__ float hadd2(u64 a) {
    float lo, hi; asm("mov.b64 {%0,%1}, %2;" : "=f"(lo), "=f"(hi) : "l"(a)); return lo + hi;
}
__device__ __forceinline__ u64 pack2f(float lo, float hi) {
    u64 u; asm("mov.b64 %0, {%1,%2};" : "=l"(u) : "f"(lo), "f"(hi)); return u;
}

__global__ void transpose_wgat_kernel(const float* __restrict__ W) {
    const int idx = blockIdx.x * 256 + threadIdx.x;       // 0 .. 98303
    const int o   = idx & 511;
    const int m   = (idx >> 9) & 63;
    const int l   = idx >> 15;
    const float lo = W[(size_t)l * 65536 + (size_t)(2 * m) * 512 + o];
    const float hi = W[(size_t)l * 65536 + (size_t)(2 * m + 1) * 512 + o];
    g_Wt[idx] = pack2f(lo, hi);
}

struct Smem {
    float nodes[TB][N_REGIONS][HIDDEN];         // 20 KB  (16B-aligned rows)
    float hh[TB][N_REGIONS][HEADS * HIDDEN];    // 80 KB
    float alpha[TB][N_REGIONS][N_REGIONS][HEADS]; // 6.4 KB
    float a[TB][N_REGIONS][HEADS][2];           // [tt][n][h][0]=a_src,[1]=a_dst
    float x[TB][80];                            // padded 70->80
    float mu[TB][N_REGIONS];
    float rstd[TB][N_REGIONS];
};

__global__ void __launch_bounds__(NTHREADS, 1) brain_graph_kernel(
    const float* __restrict__ x,
    const float* __restrict__ W_enc,
    const float* __restrict__ b_enc,
    const float* __restrict__ g_enc,
    const float* __restrict__ beta_enc,
    const float* __restrict__ att_src,
    const float* __restrict__ att_dst,
    const float* __restrict__ b_gat,
    float* __restrict__ out)
{
    extern __shared__ Smem S[];
    const int t    = threadIdx.x;        // 0..511
    const int wrp  = t >> 5;             // 0..15
    const int lane = t & 31;
    const int tok0 = blockIdx.x * TB;

    // ---- load token inputs ----
    if (t < TB * 70) {
        int tt = t / 70, c = t - tt * 70;
        S->x[tt][c] = x[(size_t)(tok0 + tt) * 70 + c];
    }
    __syncthreads();

    // ---- encoders: Linear(7,128) ----
    {
        const int tt = t >> 7, e = t & 127;
        #pragma unroll
        for (int r = 0; r < N_REGIONS; r++) {
            float acc = b_enc[r * HIDDEN + e];
            #pragma unroll
            for (int c = 0; c < CHPR; c++)
                acc += S->x[tt][r * CHPR + c] * W_enc[(r * CHPR + c) * HIDDEN + e];
            S->nodes[tt][r][e] = acc;
        }
    }
    __syncthreads();

    // ---- LayerNorm stats: 40 rows over 16 warps ----
    for (int rl = wrp; rl < TB * N_REGIONS; rl += 16) {
        const int tt = rl / N_REGIONS, r = rl - tt * N_REGIONS;
        float v0 = S->nodes[tt][r][lane];
        float v1 = S->nodes[tt][r][lane + 32];
        float v2 = S->nodes[tt][r][lane + 64];
        float v3 = S->nodes[tt][r][lane + 96];
        float s  = v0 + v1 + v2 + v3;
        float sq = v0*v0 + v1*v1 + v2*v2 + v3*v3;
        #pragma unroll
        for (int o = 16; o > 0; o >>= 1) {
            s  += __shfl_xor_sync(0xffffffffu, s,  o);
            sq += __shfl_xor_sync(0xffffffffu, sq, o);
        }
        if (lane == 0) {
            float mu  = s * (1.0f / HIDDEN);
            float var = sq * (1.0f / HIDDEN) - mu * mu;
            S->mu[tt][r]   = mu;
            S->rstd[tt][r] = rsqrtf(var + 1e-5f);
        }
    }
    __syncthreads();

    // ---- LN affine + GELU; write enc output ----
    {
        const int tt = t >> 7, e = t & 127;
        const size_t enc_base = (size_t)TOKENS * 1280 + (size_t)(tok0 + tt) * 1280;
        #pragma unroll
        for (int r = 0; r < N_REGIONS; r++) {
            float v = (S->nodes[tt][r][e] - S->mu[tt][r]) * S->rstd[tt][r]
                      * g_enc[r * HIDDEN + e] + beta_enc[r * HIDDEN + e];
            float g = gelu_exact(v);
            S->nodes[tt][r][e] = g;
            out[enc_base + r * HIDDEN + e] = g;
        }
    }
    __syncthreads();

    // ---- GAT layers ----
    for (int l = 0; l < N_LAYERS; l++) {
        // GEMM: hh[tt][r][col] = sum_k nodes[tt][r][k] * W[k][col]; col = t (0..511)
        {
            const u64* __restrict__ Wt = g_Wt + (size_t)l * 64 * 512;
            u64 acc[TB * N_REGIONS];
            #pragma unroll
            for (int i = 0; i < TB * N_REGIONS; i++) acc[i] = 0ull;

            for (int mm = 0; mm < 32; mm++) {            // 4 k per iter
                const u64 w0 = __ldg(Wt + (size_t)(2 * mm)     * 512 + t);
                const u64 w1 = __ldg(Wt + (size_t)(2 * mm + 1) * 512 + t);
                #pragma unroll
                for (int tt = 0; tt < TB; tt++) {
                    #pragma unroll
                    for (int r = 0; r < N_REGIONS; r++) {
                        const ulonglong2 nd =
                            *reinterpret_cast<const ulonglong2*>(&S->nodes[tt][r][4 * mm]);
                        u64 a0 = ffma2(nd.x, w0, acc[tt * N_REGIONS + r]);
                        acc[tt * N_REGIONS + r] = ffma2(nd.y, w1, a0);
                    }
                }
            }
            #pragma unroll
            for (int tt = 0; tt < TB; tt++)
                #pragma unroll
                for (int r = 0; r < N_REGIONS; r++)
                    S->hh[tt][r][t] = hadd2(acc[tt * N_REGIONS + r]);
        }
        __syncthreads();

        // attention scores: TB*80 = 320 length-128 dots over 16 warps
        for (int d = wrp; d < TB * N_REGIONS * HEADS * 2; d += 16) {
            const int tt  = d / 80;
            const int rem = d - tt * 80;
            const int n   = rem >> 3;
            const int h   = (rem >> 1) & 3;
            const int sd  = rem & 1;
            const float* att = (sd ? att_dst : att_src) + l * (HEADS * HIDDEN) + h * HIDDEN;
            float p = 0.0f;
            #pragma unroll
            for (int e = 0; e < HIDDEN; e += 32)
                p += S->hh[tt][n][h * HIDDEN + e + lane] * att[e + lane];
            #pragma unroll
            for (int o = 16; o > 0; o >>= 1)
                p += __shfl_xor_sync(0xffffffffu, p, o);
            if (lane == 0) S->a[tt][n][h][sd] = p;
        }
        __syncthreads();

        // softmax over neighbors: 160 (tt,i,h) units
        if (t < TB * N_REGIONS * HEADS) {
            const int tt  = t / 40;
            const int rem = t - tt * 40;
            const int i = rem >> 2, h = rem & 3;
            const int cnt = c_nbr_cnt[i];
            const float ad = S->a[tt][i][h][1];
            float lg[5];
            float mx = -1e30f;
            for (int q = 0; q < cnt; q++) {
                const int j = c_nbr[i][q];
                float v = ad + S->a[tt][j][h][0];
                v = (v >= 0.0f) ? v : 0.2f * v;
                lg[q] = v;
                mx = fmaxf(mx, v);
            }
            float sum = 0.0f;
            for (int q = 0; q < cnt; q++) { lg[q] = expf(lg[q] - mx); sum += lg[q]; }
            const float inv = 1.0f / sum;
            for (int q = 0; q < cnt; q++)
                S->alpha[tt][i][c_nbr[i][q]][h] = lg[q] * inv;
        }
        __syncthreads();

        // aggregate + mean heads + bias + GELU + residual  (thread owns (tt,e))
        {
            const int tt = t >> 7, e = t & 127;
            const float bg = b_gat[l * HIDDEN + e];
            #pragma unroll
            for (int i = 0; i < N_REGIONS; i++) {
                float acc = 0.0f;
                const int cnt = c_nbr_cnt[i];
                for (int q = 0; q < cnt; q++) {
                    const int j = c_nbr[i][q];
                    #pragma unroll
                    for (int h = 0; h < HEADS; h++)
                        acc += S->alpha[tt][i][j][h] * S->hh[tt][j][h * HIDDEN + e];
                }
                float v = acc * 0.25f + bg;
                // thread exclusively owns nodes[tt][i][e] -> safe in-place update
                S->nodes[tt][i][e] = gelu_exact(v) + S->nodes[tt][i][e];
            }
        }
        __syncthreads();
    }

    // ---- graph_features output ----
    {
        const int tt = t >> 7, e = t & 127;
        const size_t gf_base = (size_t)(tok0 + tt) * 1280;
        #pragma unroll
        for (int i = 0; i < N_REGIONS; i++)
            out[gf_base + i * HIDDEN + e] = S->nodes[tt][i][e];
    }
}

extern "C" void kernel_launch(void* const* d_in, const int* in_sizes, int n_in,
                              void* d_out, int out_size) {
    (void)in_sizes; (void)n_in; (void)out_size;
    const float* x        = (const float*)d_in[0];
    const float* W_enc    = (const float*)d_in[1];
    const float* b_enc    = (const float*)d_in[2];
    const float* g_enc    = (const float*)d_in[3];
    const float* beta_enc = (const float*)d_in[4];
    const float* W_gat    = (const float*)d_in[5];
    const float* att_src  = (const float*)d_in[6];
    const float* att_dst  = (const float*)d_in[7];
    const float* b_gat    = (const float*)d_in[8];
    float* out = (float*)d_out;

    static_assert(sizeof(Smem) < 227 * 1024, "smem overflow");
    cudaFuncSetAttribute(brain_graph_kernel,
                         cudaFuncAttributeMaxDynamicSharedMemorySize, (int)sizeof(Smem));

    transpose_wgat_kernel<<<(N_LAYERS * 64 * 512) / 256, 256>>>(W_gat);
    brain_graph_kernel<<<TOKENS / TB, NTHREADS, sizeof(Smem)>>>(
        x, W_enc, b_enc, g_enc, beta_enc, att_src, att_dst, b_gat, out);
}

// round 5
// speedup vs baseline: 1.1598x; 1.1598x over previous
#include <cuda_runtime.h>
#include <math.h>

#define N_REGIONS 10
#define HIDDEN    128
#define HEADS     4
#define N_LAYERS  3
#define CHPR      7
#define TOKENS    16384
#define TB        2            // tokens per block
#define NTHREADS  256
typedef unsigned long long u64;

__constant__ int c_nbr_cnt[N_REGIONS] = {5,5,5,3,3,4,3,4,2,2};
__constant__ int c_nbr[N_REGIONS][5] = {
    {0,1,2,3,4},{0,1,2,5,7},{0,1,2,3,7},{0,2,3,0,0},{0,4,5,0,0},
    {1,4,5,6,0},{5,6,9,0,0},{1,2,7,8,0},{7,8,0,0,0},{6,9,0,0,0}
};

// k-pair-major transposed GAT weights: g_Wt[l][m][col] = {W[2m][col], W[2m+1][col]}
__device__ u64 g_Wt[N_LAYERS * 64 * 512];

__device__ __forceinline__ float gelu_exact(float v) {
    return 0.5f * v * (1.0f + erff(v * 0.70710678118654752f));
}
__device__ __forceinline__ u64 ffma2(u64 a, u64 b, u64 c) {
    u64 d; asm("fma.rn.f32x2 %0, %1, %2, %3;" : "=l"(d) : "l"(a), "l"(b), "l"(c)); return d;
}
__device__ __forceinline__ float hadd2(u64 a) {
    float lo, hi; asm("mov.b64 {%0,%1}, %2;" : "=f"(lo), "=f"(hi) : "l"(a)); return lo + hi;
}
__device__ __forceinline__ u64 pack2f(float lo, float hi) {
    u64 u; asm("mov.b64 %0, {%1,%2};" : "=l"(u) : "f"(lo), "f"(hi)); return u;
}

__global__ void transpose_wgat_kernel(const float* __restrict__ W) {
    const int idx = blockIdx.x * 256 + threadIdx.x;       // 0 .. 98303
    const int o   = idx & 511;
    const int m   = (idx >> 9) & 63;
    const int l   = idx >> 15;
    const float lo = W[(size_t)l * 65536 + (size_t)(2 * m) * 512 + o];
    const float hi = W[(size_t)l * 65536 + (size_t)(2 * m + 1) * 512 + o];
    g_Wt[idx] = pack2f(lo, hi);
}

struct Smem {
    float nodes[TB][N_REGIONS][HIDDEN];           // 10 KB (16B-aligned rows)
    float hh[TB][N_REGIONS][HEADS * HIDDEN];      // 40 KB
    float alpha[TB][N_REGIONS][N_REGIONS][HEADS]; // 3.2 KB
    float a[TB][N_REGIONS][HEADS][2];
    float x[TB][72];
    float mu[TB][N_REGIONS];
    float rstd[TB][N_REGIONS];
};

__global__ void __launch_bounds__(NTHREADS, 2) brain_graph_kernel(
    const float* __restrict__ x,
    const float* __restrict__ W_enc,
    const float* __restrict__ b_enc,
    const float* __restrict__ g_enc,
    const float* __restrict__ beta_enc,
    const float* __restrict__ att_src,
    const float* __restrict__ att_dst,
    const float* __restrict__ b_gat,
    float* __restrict__ out)
{
    extern __shared__ Smem S[];
    const int t    = threadIdx.x;        // 0..255
    const int wrp  = t >> 5;             // 0..7
    const int lane = t & 31;
    const int tok0 = blockIdx.x * TB;

    // thread owns (tt=gt, e=c) for elementwise phases; GEMM: token gt, cols c+128p
    const int gt = t >> 7;               // 0..1  (warps 0-3 -> token 0, 4-7 -> token 1)
    const int c  = t & 127;

    // ---- load token inputs ----
    if (t < TB * 70) {
        int tt = t / 70, ch = t - tt * 70;
        S->x[tt][ch] = x[(size_t)(tok0 + tt) * 70 + ch];
    }
    __syncthreads();

    // ---- encoders: Linear(7,128); one (tt,e) per thread ----
    {
        #pragma unroll
        for (int r = 0; r < N_REGIONS; r++) {
            float acc = b_enc[r * HIDDEN + c];
            #pragma unroll
            for (int ch = 0; ch < CHPR; ch++)
                acc += S->x[gt][r * CHPR + ch] * W_enc[(r * CHPR + ch) * HIDDEN + c];
            S->nodes[gt][r][c] = acc;
        }
    }
    __syncthreads();

    // ---- LayerNorm stats: 20 rows over 8 warps ----
    for (int rl = wrp; rl < TB * N_REGIONS; rl += 8) {
        const int tt = rl / N_REGIONS, r = rl - tt * N_REGIONS;
        float v0 = S->nodes[tt][r][lane];
        float v1 = S->nodes[tt][r][lane + 32];
        float v2 = S->nodes[tt][r][lane + 64];
        float v3 = S->nodes[tt][r][lane + 96];
        float s  = v0 + v1 + v2 + v3;
        float sq = v0*v0 + v1*v1 + v2*v2 + v3*v3;
        #pragma unroll
        for (int o = 16; o > 0; o >>= 1) {
            s  += __shfl_xor_sync(0xffffffffu, s,  o);
            sq += __shfl_xor_sync(0xffffffffu, sq, o);
        }
        if (lane == 0) {
            float mu  = s * (1.0f / HIDDEN);
            float var = sq * (1.0f / HIDDEN) - mu * mu;
            S->mu[tt][r]   = mu;
            S->rstd[tt][r] = rsqrtf(var + 1e-5f);
        }
    }
    __syncthreads();

    // ---- LN affine + GELU; write enc output ----
    {
        const size_t enc_base = (size_t)TOKENS * 1280 + (size_t)(tok0 + gt) * 1280;
        #pragma unroll
        for (int r = 0; r < N_REGIONS; r++) {
            float v = (S->nodes[gt][r][c] - S->mu[gt][r]) * S->rstd[gt][r]
                      * g_enc[r * HIDDEN + c] + beta_enc[r * HIDDEN + c];
            float g = gelu_exact(v);
            S->nodes[gt][r][c] = g;
            out[enc_base + r * HIDDEN + c] = g;
        }
    }
    __syncthreads();

    // ---- GAT layers ----
    for (int l = 0; l < N_LAYERS; l++) {
        // GEMM: hh[gt][r][col] = sum_k nodes[gt][r][k]*W[k][col]
        // thread owns token gt, columns c + 128*p (p=0..3); acc = {even-k, odd-k} partials
        {
            const u64* __restrict__ Wt = g_Wt + (size_t)l * 64 * 512;
            u64 acc[N_REGIONS][4];
            #pragma unroll
            for (int r = 0; r < N_REGIONS; r++)
                #pragma unroll
                for (int p = 0; p < 4; p++) acc[r][p] = 0ull;

            #pragma unroll 1
            for (int mm = 0; mm < 32; mm++) {            // 4 k per iter
                u64 w0[4], w1[4];
                #pragma unroll
                for (int p = 0; p < 4; p++) {
                    w0[p] = __ldg(Wt + (size_t)(2 * mm)     * 512 + c + 128 * p);
                    w1[p] = __ldg(Wt + (size_t)(2 * mm + 1) * 512 + c + 128 * p);
                }
                #pragma unroll
                for (int r = 0; r < N_REGIONS; r++) {
                    const ulonglong2 nd =
                        *reinterpret_cast<const ulonglong2*>(&S->nodes[gt][r][4 * mm]);
                    #pragma unroll
                    for (int p = 0; p < 4; p++) {
                        acc[r][p] = ffma2(nd.x, w0[p], acc[r][p]);
                        acc[r][p] = ffma2(nd.y, w1[p], acc[r][p]);
                    }
                }
            }
            #pragma unroll
            for (int r = 0; r < N_REGIONS; r++)
                #pragma unroll
                for (int p = 0; p < 4; p++)
                    S->hh[gt][r][c + 128 * p] = hadd2(acc[r][p]);
        }
        __syncthreads();

        // attention scores: TB*80 = 160 length-128 dots over 8 warps
        for (int d = wrp; d < TB * N_REGIONS * HEADS * 2; d += 8) {
            const int tt  = d / 80;
            const int rem = d - tt * 80;
            const int n   = rem >> 3;
            const int h   = (rem >> 1) & 3;
            const int sd  = rem & 1;
            const float* att = (sd ? att_dst : att_src) + l * (HEADS * HIDDEN) + h * HIDDEN;
            float p = 0.0f;
            #pragma unroll
            for (int e = 0; e < HIDDEN; e += 32)
                p += S->hh[tt][n][h * HIDDEN + e + lane] * att[e + lane];
            #pragma unroll
            for (int o = 16; o > 0; o >>= 1)
                p += __shfl_xor_sync(0xffffffffu, p, o);
            if (lane == 0) S->a[tt][n][h][sd] = p;
        }
        __syncthreads();

        // softmax over neighbors: 80 (tt,i,h) units
        if (t < TB * N_REGIONS * HEADS) {
            const int tt  = t / 40;
            const int rem = t - tt * 40;
            const int i = rem >> 2, h = rem & 3;
            const int cnt = c_nbr_cnt[i];
            const float ad = S->a[tt][i][h][1];
            float lg[5];
            float mx = -1e30f;
            for (int q = 0; q < cnt; q++) {
                const int j = c_nbr[i][q];
                float v = ad + S->a[tt][j][h][0];
                v = (v >= 0.0f) ? v : 0.2f * v;
                lg[q] = v;
                mx = fmaxf(mx, v);
            }
            float sum = 0.0f;
            for (int q = 0; q < cnt; q++) { lg[q] = expf(lg[q] - mx); sum += lg[q]; }
            const float inv = 1.0f / sum;
            for (int q = 0; q < cnt; q++)
                S->alpha[tt][i][c_nbr[i][q]][h] = lg[q] * inv;
        }
        __syncthreads();

        // aggregate + mean heads + bias + GELU + residual: thread owns (gt, c)
        {
            const float bg = b_gat[l * HIDDEN + c];
            #pragma unroll
            for (int i = 0; i < N_REGIONS; i++) {
                float acc = 0.0f;
                const int cnt = c_nbr_cnt[i];
                for (int q = 0; q < cnt; q++) {
                    const int j = c_nbr[i][q];
                    #pragma unroll
                    for (int h = 0; h < HEADS; h++)
                        acc += S->alpha[gt][i][j][h] * S->hh[gt][j][h * HIDDEN + c];
                }
                float v = acc * 0.25f + bg;
                S->nodes[gt][i][c] = gelu_exact(v) + S->nodes[gt][i][c];
            }
        }
        __syncthreads();
    }

    // ---- graph_features output ----
    {
        const size_t gf_base = (size_t)(tok0 + gt) * 1280;
        #pragma unroll
        for (int i = 0; i < N_REGIONS; i++)
            out[gf_base + i * HIDDEN + c] = S->nodes[gt][i][c];
    }
}

extern "C" void kernel_launch(void* const* d_in, const int* in_sizes, int n_in,
                              void* d_out, int out_size) {
    (void)in_sizes; (void)n_in; (void)out_size;
    const float* x        = (const float*)d_in[0];
    const float* W_enc    = (const float*)d_in[1];
    const float* b_enc    = (const float*)d_in[2];
    const float* g_enc    = (const float*)d_in[3];
    const float* beta_enc = (const float*)d_in[4];
    const float* W_gat    = (const float*)d_in[5];
    const float* att_src  = (const float*)d_in[6];
    const float* att_dst  = (const float*)d_in[7];
    const float* b_gat    = (const float*)d_in[8];
    float* out = (float*)d_out;

    static_assert(sizeof(Smem) < 57 * 1024, "smem too big for 2 blocks/SM");
    cudaFuncSetAttribute(brain_graph_kernel,
                         cudaFuncAttributeMaxDynamicSharedMemorySize, (int)sizeof(Smem));

    transpose_wgat_kernel<<<(N_LAYERS * 64 * 512) / 256, 256>>>(W_gat);
    brain_graph_kernel<<<TOKENS / TB, NTHREADS, sizeof(Smem)>>>(
        x, W_enc, b_enc, g_enc, beta_enc, att_src, att_dst, b_gat, out);
}